// round 8
// baseline (speedup 1.0000x reference)
#include <cuda_runtime.h>
#include <math.h>

#define Hh 128
#define CB 32
#define PAD 36
#define HS_L (Hh*PAD)
#define NTHREADS 1024
#define NBLOCKS 128

// Output layout (concatenated return tuple, float32):
// decoder_output (4096,100,4) | dec_hidden (4,4096,128) | encoder_output (4096,64,128) | enc_hidden (4,4096,128) | loss (1)
#define DEC_OUT_OFF 0ul
#define DEC_HID_OFF 1638400ul
#define ENC_OUT_OFF 3735552ul
#define ENC_HID_OFF 37289984ul
#define LOSS_OFF    39387136ul

// Packed weight scratch (floats).
// L0H: [k(128)][j(128)][4] = {whr,whz,whn,0}
// L0X: [k(4)][j(128)][4]   = {wxr,wxz,wxn,0}
// F:   [k(128)][j(128)][8] = {whr,whz,whn,wxr,wxz,wxn,0,0}
// LIN1:[k(128)][i(128)]
#define ENC_L0H 0
#define ENC_L0X 65536
#define DEC_L0H 67584
#define DEC_L0X 133120
#define ENC_F   135168
#define DEC_F   528384
#define LIN1_T  921600
#define WT_TOTAL 937984

__device__ float g_wt[WT_TOTAL];

// ---------------- packed f32x2 helpers ----------------

typedef unsigned long long u64;

__device__ __forceinline__ u64 pack2s(float v)
{
    u64 r;
    asm("mov.b64 %0,{%1,%1};" : "=l"(r) : "f"(v));
    return r;
}
__device__ __forceinline__ void unpack2(u64 v, float& lo, float& hi)
{
    asm("mov.b64 {%0,%1},%2;" : "=f"(lo), "=f"(hi) : "l"(v));
}
__device__ __forceinline__ void ffma2(u64& d, u64 a, u64 b)
{
    asm("fma.rn.f32x2 %0,%1,%2,%3;" : "=l"(d) : "l"(a), "l"(b), "l"(d));
}

// ---------------- prep kernels ----------------

// whh0 [3*128][128] -> L0-style h pack at dstOff
__global__ void k_pack_h0(const float* __restrict__ whh0, int dstOff)
{
    for (int idx = blockIdx.x * blockDim.x + threadIdx.x; idx < 128 * 128;
         idx += gridDim.x * blockDim.x) {
        int k = idx >> 7, j = idx & 127;
        float* d = g_wt + dstOff + idx * 4;
        d[0] = whh0[(0 * 128 + j) * 128 + k];
        d[1] = whh0[(1 * 128 + j) * 128 + k];
        d[2] = whh0[(2 * 128 + j) * 128 + k];
        d[3] = 0.0f;
    }
}

// wih0 [3*128][4] -> L0X pack at dstOff
__global__ void k_pack_x0(const float* __restrict__ wih0, int dstOff)
{
    for (int idx = blockIdx.x * blockDim.x + threadIdx.x; idx < 4 * 128;
         idx += gridDim.x * blockDim.x) {
        int k = idx >> 7, j = idx & 127;
        float* d = g_wt + dstOff + idx * 4;
        d[0] = wih0[(0 * 128 + j) * 4 + k];
        d[1] = wih0[(1 * 128 + j) * 4 + k];
        d[2] = wih0[(2 * 128 + j) * 4 + k];
        d[3] = 0.0f;
    }
}

// wih/whh [3*128][128] -> fused 8-float records at dstOff
__global__ void k_pack_fused(const float* __restrict__ wih,
                             const float* __restrict__ whh, int dstOff)
{
    for (int idx = blockIdx.x * blockDim.x + threadIdx.x; idx < 128 * 128;
         idx += gridDim.x * blockDim.x) {
        int k = idx >> 7, j = idx & 127;
        float* d = g_wt + dstOff + idx * 8;
        d[0] = whh[(0 * 128 + j) * 128 + k];
        d[1] = whh[(1 * 128 + j) * 128 + k];
        d[2] = whh[(2 * 128 + j) * 128 + k];
        d[3] = wih[(0 * 128 + j) * 128 + k];
        d[4] = wih[(1 * 128 + j) * 128 + k];
        d[5] = wih[(2 * 128 + j) * 128 + k];
        d[6] = 0.0f;
        d[7] = 0.0f;
    }
}

// lin1_w [H][H] -> g_wt[LIN1_T + k*H + i]
__global__ void k_tr_lin1(const float* __restrict__ src)
{
    for (int idx = blockIdx.x * blockDim.x + threadIdx.x; idx < Hh * Hh;
         idx += gridDim.x * blockDim.x) {
        int i = idx >> 7;
        int k = idx & (Hh - 1);
        g_wt[LIN1_T + k * Hh + i] = src[idx];
    }
}

__global__ void k_zero_loss(float* __restrict__ out)
{
    if (threadIdx.x == 0) out[LOSS_OFF] = 0.0f;
}

// ---------------- main kernel ----------------

__device__ __forceinline__ float sigf(float x)
{
    return 1.0f / (1.0f + __expf(-x));
}

__device__ __forceinline__ float tanhfast(float x)
{
    float t = __expf(2.0f * x);
    return 1.0f - 2.0f / (t + 1.0f);   // safe at +/- inf
}

// Pointwise GRU gate update for this thread's 4 batch elements.
__device__ __forceinline__ void gru_pointwise(
    u64* ar, u64* az, u64* ain, u64* ahn, float* hrow0)
{
#pragma unroll
    for (int p = 0; p < 2; p++) {
        float r0, r1, z0, z1, i0, i1, n0, n1;
        unpack2(ar[p], r0, r1);
        unpack2(az[p], z0, z1);
        unpack2(ain[p], i0, i1);
        unpack2(ahn[p], n0, n1);
        float h0 = hrow0[2 * p];
        float h1 = hrow0[2 * p + 1];
        float rr0 = sigf(r0), rr1 = sigf(r1);
        float zz0 = sigf(z0), zz1 = sigf(z1);
        float nn0 = tanhfast(fmaf(rr0, n0, i0));
        float nn1 = tanhfast(fmaf(rr1, n1, i1));
        hrow0[2 * p]     = fmaf(zz0, h0 - nn0, nn0);
        hrow0[2 * p + 1] = fmaf(zz1, h1 - nn1, nn1);
    }
}

// Fused GRU layer (input dim = 128, input activations xs = previous layer h).
__device__ __forceinline__ void gru_layer_f(
    const float* __restrict__ wf,
    const float* __restrict__ bih, const float* __restrict__ bhh,
    const float* __restrict__ xs, float* __restrict__ hsl,
    int j, int bB)
{
    u64 ar[2], az[2], ain[2], ahn[2];
    {
        u64 br  = pack2s(bih[j] + bhh[j]);
        u64 bz  = pack2s(bih[Hh + j] + bhh[Hh + j]);
        u64 bi  = pack2s(bih[2 * Hh + j]);
        u64 bh2 = pack2s(bhh[2 * Hh + j]);
#pragma unroll
        for (int p = 0; p < 2; p++) {
            ar[p] = br; az[p] = bz; ain[p] = bi; ahn[p] = bh2;
        }
    }
    const float* wb = wf + j * 8;
    float4 wa = *(const float4*)(wb);
    float2 wc = *(const float2*)(wb + 4);
#pragma unroll 4
    for (int k = 0; k < Hh; k++) {
        float4 wa_c = wa;
        float2 wc_c = wc;
        int kn = (k + 1) & 127;
        wa = *(const float4*)(wb + kn * 1024);
        wc = *(const float2*)(wb + kn * 1024 + 4);
        u64 wr = pack2s(wa_c.x), wz = pack2s(wa_c.y), wn = pack2s(wa_c.z);
        u64 vr = pack2s(wa_c.w), vz = pack2s(wc_c.x), vn = pack2s(wc_c.y);
        ulonglong2 ha = *(const ulonglong2*)(hsl + k * PAD + bB);
        ulonglong2 xa = *(const ulonglong2*)(xs + k * PAD + bB);
        u64 hv[2] = {ha.x, ha.y};
        u64 xv[2] = {xa.x, xa.y};
#pragma unroll
        for (int p = 0; p < 2; p++) {
            ffma2(ar[p], hv[p], wr);
            ffma2(az[p], hv[p], wz);
            ffma2(ahn[p], hv[p], wn);
            ffma2(ar[p], xv[p], vr);
            ffma2(az[p], xv[p], vz);
            ffma2(ain[p], xv[p], vn);
        }
    }
    __syncthreads();   // all reads of hsl done before overwrite
    gru_pointwise(ar, az, ain, ahn, hsl + j * PAD + bB);
    __syncthreads();   // hsl ready for next layer
}

// Layer 0 (input dim 4 from x0s).
__device__ __forceinline__ void gru_layer_0(
    const float* __restrict__ wh0, const float* __restrict__ wx0,
    const float* __restrict__ bih, const float* __restrict__ bhh,
    const float* __restrict__ xs, float* __restrict__ hsl,
    int j, int bB)
{
    u64 ar[2], az[2], ain[2], ahn[2];
    {
        u64 br  = pack2s(bih[j] + bhh[j]);
        u64 bz  = pack2s(bih[Hh + j] + bhh[Hh + j]);
        u64 bi  = pack2s(bih[2 * Hh + j]);
        u64 bh2 = pack2s(bhh[2 * Hh + j]);
#pragma unroll
        for (int p = 0; p < 2; p++) {
            ar[p] = br; az[p] = bz; ain[p] = bi; ahn[p] = bh2;
        }
    }
    const float* wb = wh0 + j * 4;
    float4 wa = *(const float4*)(wb);
#pragma unroll 4
    for (int k = 0; k < Hh; k++) {
        float4 wa_c = wa;
        int kn = (k + 1) & 127;
        wa = *(const float4*)(wb + kn * 512);
        u64 wr = pack2s(wa_c.x), wz = pack2s(wa_c.y), wn = pack2s(wa_c.z);
        ulonglong2 ha = *(const ulonglong2*)(hsl + k * PAD + bB);
        u64 hv[2] = {ha.x, ha.y};
#pragma unroll
        for (int p = 0; p < 2; p++) {
            ffma2(ar[p], hv[p], wr);
            ffma2(az[p], hv[p], wz);
            ffma2(ahn[p], hv[p], wn);
        }
    }
    const float* xb = wx0 + j * 4;
#pragma unroll
    for (int k = 0; k < 4; k++) {
        float4 va = *(const float4*)(xb + k * 512);
        u64 vr = pack2s(va.x), vz = pack2s(va.y), vn = pack2s(va.z);
        ulonglong2 xa = *(const ulonglong2*)(xs + k * PAD + bB);
        u64 xv[2] = {xa.x, xa.y};
#pragma unroll
        for (int p = 0; p < 2; p++) {
            ffma2(ar[p], xv[p], vr);
            ffma2(az[p], xv[p], vz);
            ffma2(ain[p], xv[p], vn);
        }
    }
    __syncthreads();
    gru_pointwise(ar, az, ain, ahn, hsl + j * PAD + bB);
    __syncthreads();
}

__global__ void __launch_bounds__(NTHREADS, 1) gru_main(
    const float* __restrict__ inp, const float* __restrict__ tgt,
    const float* __restrict__ enc_bih, const float* __restrict__ enc_bhh,
    const float* __restrict__ dec_bih, const float* __restrict__ dec_bhh,
    const float* __restrict__ lin1_b, const float* __restrict__ lin2_w,
    const float* __restrict__ lin2_b,
    float* __restrict__ out)
{
    extern __shared__ float sm[];
    float* hs  = sm;                        // [4][H][PAD]
    float* o1s = sm + 4 * HS_L;             // [H][PAD]
    float* x0s = o1s + HS_L;                // [4][PAD]
    float* red = x0s + 4 * PAD;             // [NTHREADS]

    const int tid  = threadIdx.x;
    const int lane = tid & 31;
    const int w    = tid >> 5;
    const int j    = ((w & 3) << 5) | lane;
    const int bB   = (w >> 2) << 2;         // 4 batch elements per thread
    const int b0   = blockIdx.x * CB;

    for (int u = tid; u < 4 * HS_L; u += NTHREADS) hs[u] = 0.0f;
    if (tid < CB * 4) {
        int b = tid >> 2, e = tid & 3;
        out[DEC_OUT_OFF + (size_t)(b0 + b) * 400 + e] =
            inp[(size_t)(b0 + b) * 256 + e];
    }
    __syncthreads();

    // ---------------- encoder: 64 steps ----------------
    for (int t = 0; t < 64; t++) {
        if (tid < CB * 4) {
            int b = tid >> 2, e = tid & 3;
            x0s[e * PAD + b] = inp[(size_t)(b0 + b) * 256 + t * 4 + e];
        }
        __syncthreads();
        gru_layer_0(g_wt + ENC_L0H, g_wt + ENC_L0X,
                    enc_bih, enc_bhh, x0s, hs, j, bB);
#pragma unroll 1
        for (int l = 1; l < 4; l++) {
            gru_layer_f(g_wt + ENC_F + (l - 1) * 131072,
                        enc_bih + l * 384, enc_bhh + l * 384,
                        hs + (l - 1) * HS_L, hs + l * HS_L, j, bB);
        }
        const float* h3 = hs + 3 * HS_L;
        for (int u = tid; u < CB * Hh; u += NTHREADS) {
            int b = u >> 7, k = u & 127;
            out[ENC_OUT_OFF + (size_t)(b0 + b) * 8192 + t * 128 + k] =
                h3[k * PAD + b];
        }
        // no barrier needed: next write to hs[3] / x0s is many barriers away
    }
    // enc_hidden (L,B,H)
    for (int u = tid; u < 4 * CB * Hh; u += NTHREADS) {
        int l = u >> 12, r = u & 4095, b = r >> 7, k = r & 127;
        out[ENC_HID_OFF + (size_t)l * 524288 + (size_t)(b0 + b) * 128 + k] =
            hs[l * HS_L + k * PAD + b];
    }

    // ---------------- decoder: 99 steps ----------------
    float lossAcc = 0.0f;
    for (int s = 0; s < 99; s++) {
        if (tid < CB * 4) {
            int b = tid >> 2, e = tid & 3;
            float xv = (s == 0) ? inp[(size_t)(b0 + b) * 256 + e]
                                : tgt[(size_t)(b0 + b) * 400 + s * 4 + e];
            x0s[e * PAD + b] = xv;
        }
        __syncthreads();
        gru_layer_0(g_wt + DEC_L0H, g_wt + DEC_L0X,
                    dec_bih, dec_bhh, x0s, hs, j, bB);
#pragma unroll 1
        for (int l = 1; l < 4; l++) {
            gru_layer_f(g_wt + DEC_F + (l - 1) * 131072,
                        dec_bih + l * 384, dec_bhh + l * 384,
                        hs + (l - 1) * HS_L, hs + l * HS_L, j, bB);
        }
        // lin1 + relu -> o1s
        {
            u64 acc[2];
            u64 bi = pack2s(lin1_b[j]);
            acc[0] = bi; acc[1] = bi;
            const float* top = hs + 3 * HS_L;
            const float* wt1 = g_wt + LIN1_T + j;
            float wv_f = wt1[0];
#pragma unroll 4
            for (int k = 0; k < Hh; k++) {
                float wv_c = wv_f;
                int kn = (k + 1) & 127;
                wv_f = wt1[kn * Hh];
                u64 wv = pack2s(wv_c);
                ulonglong2 ta = *(const ulonglong2*)(top + k * PAD + bB);
                ffma2(acc[0], ta.x, wv);
                ffma2(acc[1], ta.y, wv);
            }
            float* orow = o1s + j * PAD + bB;
#pragma unroll
            for (int p = 0; p < 2; p++) {
                float a0, a1;
                unpack2(acc[p], a0, a1);
                orow[2 * p]     = fmaxf(a0, 0.0f);
                orow[2 * p + 1] = fmaxf(a1, 0.0f);
            }
        }
        __syncthreads();
        // lin2 + loss + store
        if (tid < CB * 4) {
            int b = tid >> 2, e = tid & 3;
            float acc = lin2_b[e];
#pragma unroll 4
            for (int i = 0; i < Hh; i++)
                acc = fmaf(o1s[i * PAD + b], lin2_w[e * Hh + i], acc);
            float y = tgt[(size_t)(b0 + b) * 400 + (s + 1) * 4 + e];
            float d = acc - y;
            lossAcc += d * d;
            out[DEC_OUT_OFF + (size_t)(b0 + b) * 400 + (s + 1) * 4 + e] = acc;
        }
        __syncthreads();   // o1s reads done before next step's lin1 writes
    }
    // dec_hidden (L,B,H)
    for (int u = tid; u < 4 * CB * Hh; u += NTHREADS) {
        int l = u >> 12, r = u & 4095, b = r >> 7, k = r & 127;
        out[DEC_HID_OFF + (size_t)l * 524288 + (size_t)(b0 + b) * 128 + k] =
            hs[l * HS_L + k * PAD + b];
    }

    // loss reduction
    red[tid] = lossAcc;
    __syncthreads();
    for (int s2 = NTHREADS / 2; s2 > 0; s2 >>= 1) {
        if (tid < s2) red[tid] += red[tid + s2];
        __syncthreads();
    }
    if (tid == 0) atomicAdd(out + LOSS_OFF, red[0] * (1.0f / 16384.0f));
}

// ---------------- launch ----------------

extern "C" void kernel_launch(void* const* d_in, const int* in_sizes, int n_in,
                              void* d_out, int out_size)
{
    const float* inp      = (const float*)d_in[0];
    const float* tgt      = (const float*)d_in[1];
    const float* enc_wih0 = (const float*)d_in[2];
    const float* enc_whh0 = (const float*)d_in[3];
    const float* enc_wih  = (const float*)d_in[4];
    const float* enc_whh  = (const float*)d_in[5];
    const float* enc_bih  = (const float*)d_in[6];
    const float* enc_bhh  = (const float*)d_in[7];
    const float* dec_wih0 = (const float*)d_in[8];
    const float* dec_whh0 = (const float*)d_in[9];
    const float* dec_wih  = (const float*)d_in[10];
    const float* dec_whh  = (const float*)d_in[11];
    const float* dec_bih  = (const float*)d_in[12];
    const float* dec_bhh  = (const float*)d_in[13];
    const float* lin1_w   = (const float*)d_in[14];
    const float* lin1_b   = (const float*)d_in[15];
    const float* lin2_w   = (const float*)d_in[16];
    const float* lin2_b   = (const float*)d_in[17];
    float* out = (float*)d_out;

    const int smemBytes = (4 * HS_L + HS_L + 4 * PAD + NTHREADS) * 4;
    cudaFuncSetAttribute(gru_main, cudaFuncAttributeMaxDynamicSharedMemorySize,
                         smemBytes);

    k_zero_loss<<<1, 32>>>(out);

    k_pack_h0<<<32, 512>>>(enc_whh0, ENC_L0H);
    k_pack_x0<<<1, 512>>>(enc_wih0, ENC_L0X);
    k_pack_h0<<<32, 512>>>(dec_whh0, DEC_L0H);
    k_pack_x0<<<1, 512>>>(dec_wih0, DEC_L0X);
    for (int l = 0; l < 3; l++) {
        k_pack_fused<<<32, 512>>>(enc_wih + l * 49152, enc_whh + l * 49152,
                                  ENC_F + l * 131072);
        k_pack_fused<<<32, 512>>>(dec_wih + l * 49152, dec_whh + l * 49152,
                                  DEC_F + l * 131072);
    }
    k_tr_lin1<<<32, 512>>>(lin1_w);

    gru_main<<<NBLOCKS, NTHREADS, smemBytes>>>(
        inp, tgt, enc_bih, enc_bhh, dec_bih, dec_bhh,
        lin1_b, lin2_w, lin2_b, out);
}

// round 10
// speedup vs baseline: 1.5135x; 1.5135x over previous
#include <cuda_runtime.h>
#include <math.h>

#define Hh 128
#define CB 32
#define DUPW 68
#define NTHREADS 512
#define NBLOCKS 128

// Output layout (concatenated return tuple, float32):
// decoder_output (4096,100,4) | dec_hidden (4,4096,128) | encoder_output (4096,64,128) | enc_hidden (4,4096,128) | loss (1)
#define DEC_OUT_OFF 0ul
#define DEC_HID_OFF 1638400ul
#define ENC_OUT_OFF 3735552ul
#define ENC_HID_OFF 37289984ul
#define LOSS_OFF    39387136ul

// Packed weight scratch (floats). All j-PAIR packed: jp in 0..63, j0=2jp, j1=2jp+1.
// Fused layer (per layer, 98304 floats):
//   WA [k128][jp64][4] = {whr(j0),whr(j1),whz(j0),whz(j1)}
//   WB [k128][jp64][4] = {whn(j0),whn(j1),wxr(j0),wxr(j1)}
//   WC [k128][jp64][4] = {wxz(j0),wxz(j1),wxn(j0),wxn(j1)}
// L0: HA [k128][jp][4]={hr0,hr1,hz0,hz1}  HB [k128][jp][2]={hn0,hn1}
//     XA [k4][jp][4]={xr0,xr1,xz0,xz1}    XB [k4][jp][2]={xn0,xn1}
// LIN1P [k128][jp][2] = {w(j0),w(j1)}
#define ENC_F    0
#define DEC_F    294912
#define ENC_L0HA 589824
#define ENC_L0HB 622592
#define ENC_L0XA 638976
#define ENC_L0XB 640000
#define DEC_L0HA 640512
#define DEC_L0HB 673280
#define DEC_L0XA 689664
#define DEC_L0XB 690688
#define LIN1P    691200
#define WT_TOTAL 707584

__device__ float g_wt[WT_TOTAL];

// ---------------- f32x2 helpers ----------------

typedef unsigned long long u64;

__device__ __forceinline__ void unpack2(u64 v, float& lo, float& hi)
{
    asm("mov.b64 {%0,%1},%2;" : "=f"(lo), "=f"(hi) : "l"(v));
}
__device__ __forceinline__ void ffma2(u64& d, u64 a, u64 b)
{
    asm("fma.rn.f32x2 %0,%1,%2,%3;" : "=l"(d) : "l"(a), "l"(b), "l"(d));
}
__device__ __forceinline__ u64 addx2(u64 a, u64 b)
{
    u64 r;
    asm("add.rn.f32x2 %0,%1,%2;" : "=l"(r) : "l"(a), "l"(b));
    return r;
}
__device__ __forceinline__ u64 ldu64(const float* p)
{
    return *(const u64*)p;
}

// ---------------- prep kernels ----------------

// fused layer pack: wih/whh are [3*128][128] row-major
__global__ void k_pack_fused(const float* __restrict__ wih,
                             const float* __restrict__ whh, int dstOff)
{
    for (int idx = blockIdx.x * blockDim.x + threadIdx.x; idx < 128 * 64;
         idx += gridDim.x * blockDim.x) {
        int k = idx >> 6, jp = idx & 63;
        int j0 = 2 * jp, j1 = j0 + 1;
        float* A = g_wt + dstOff + idx * 4;
        float* B = g_wt + dstOff + 32768 + idx * 4;
        float* C = g_wt + dstOff + 65536 + idx * 4;
        A[0] = whh[(0 * 128 + j0) * 128 + k];
        A[1] = whh[(0 * 128 + j1) * 128 + k];
        A[2] = whh[(1 * 128 + j0) * 128 + k];
        A[3] = whh[(1 * 128 + j1) * 128 + k];
        B[0] = whh[(2 * 128 + j0) * 128 + k];
        B[1] = whh[(2 * 128 + j1) * 128 + k];
        B[2] = wih[(0 * 128 + j0) * 128 + k];
        B[3] = wih[(0 * 128 + j1) * 128 + k];
        C[0] = wih[(1 * 128 + j0) * 128 + k];
        C[1] = wih[(1 * 128 + j1) * 128 + k];
        C[2] = wih[(2 * 128 + j0) * 128 + k];
        C[3] = wih[(2 * 128 + j1) * 128 + k];
    }
}

// L0 pack: whh0 [3*128][128], wih0 [3*128][4]
__global__ void k_pack_l0(const float* __restrict__ wih0,
                          const float* __restrict__ whh0,
                          int dHA, int dHB, int dXA, int dXB)
{
    for (int idx = blockIdx.x * blockDim.x + threadIdx.x; idx < 128 * 64;
         idx += gridDim.x * blockDim.x) {
        int k = idx >> 6, jp = idx & 63;
        int j0 = 2 * jp, j1 = j0 + 1;
        float* A = g_wt + dHA + idx * 4;
        float* B = g_wt + dHB + idx * 2;
        A[0] = whh0[(0 * 128 + j0) * 128 + k];
        A[1] = whh0[(0 * 128 + j1) * 128 + k];
        A[2] = whh0[(1 * 128 + j0) * 128 + k];
        A[3] = whh0[(1 * 128 + j1) * 128 + k];
        B[0] = whh0[(2 * 128 + j0) * 128 + k];
        B[1] = whh0[(2 * 128 + j1) * 128 + k];
        if (idx < 4 * 64) {
            int kx = idx >> 6;   // 0..3
            float* XA = g_wt + dXA + idx * 4;
            float* XB = g_wt + dXB + idx * 2;
            XA[0] = wih0[(0 * 128 + j0) * 4 + kx];
            XA[1] = wih0[(0 * 128 + j1) * 4 + kx];
            XA[2] = wih0[(1 * 128 + j0) * 4 + kx];
            XA[3] = wih0[(1 * 128 + j1) * 4 + kx];
            XB[0] = wih0[(2 * 128 + j0) * 4 + kx];
            XB[1] = wih0[(2 * 128 + j1) * 4 + kx];
        }
    }
}

// lin1_w [i][k] -> LIN1P [k][jp][2]
__global__ void k_pack_lin1(const float* __restrict__ src)
{
    for (int idx = blockIdx.x * blockDim.x + threadIdx.x; idx < 128 * 64;
         idx += gridDim.x * blockDim.x) {
        int k = idx >> 6, jp = idx & 63;
        g_wt[LIN1P + idx * 2]     = src[(2 * jp) * 128 + k];
        g_wt[LIN1P + idx * 2 + 1] = src[(2 * jp + 1) * 128 + k];
    }
}

__global__ void k_zero_loss(float* __restrict__ out)
{
    if (threadIdx.x == 0) out[LOSS_OFF] = 0.0f;
}

// ---------------- main kernel ----------------

__device__ __forceinline__ float sigf(float x)
{
    return 1.0f / (1.0f + __expf(-x));
}

__device__ __forceinline__ float tanhfast(float x)
{
    float t = __expf(2.0f * x);
    return 1.0f - 2.0f / (t + 1.0f);   // safe at +/- inf
}

// Pointwise update: acc pairs are {j0,j1}; writes duplicated h values.
__device__ __forceinline__ void gru_pointwise(
    u64* ar, u64* az, u64* ain, u64* ahn, float* hsl, int j0, int bB)
{
    float* row0 = hsl + j0 * DUPW;
    float* row1 = hsl + (j0 + 1) * DUPW;
#pragma unroll
    for (int p = 0; p < 4; p++) {
        float r0, r1, z0, z1, i0, i1, n0, n1;
        unpack2(ar[p], r0, r1);
        unpack2(az[p], z0, z1);
        unpack2(ain[p], i0, i1);
        unpack2(ahn[p], n0, n1);
        int c = 2 * (bB + p);
        float h0 = row0[c], h1 = row1[c];
        float rr0 = sigf(r0), rr1 = sigf(r1);
        float zz0 = sigf(z0), zz1 = sigf(z1);
        float nn0 = tanhfast(fmaf(rr0, n0, i0));
        float nn1 = tanhfast(fmaf(rr1, n1, i1));
        float v0 = fmaf(zz0, h0 - nn0, nn0);
        float v1 = fmaf(zz1, h1 - nn1, nn1);
        row0[c] = v0; row0[c + 1] = v0;
        row1[c] = v1; row1[c + 1] = v1;
    }
}

// Fused GRU layer (input = prev layer h, duplicated smem layout).
__device__ __forceinline__ void gru_layer_f(
    const float* __restrict__ wf,
    const float* __restrict__ bih, const float* __restrict__ bhh,
    const float* __restrict__ xsd, float* __restrict__ hsd,
    int jp, int bB)
{
    const int j0 = 2 * jp;
    u64 ar[4], az[4], ain[4], ahn[4];
    {
        u64 br = addx2(ldu64(bih + j0), ldu64(bhh + j0));
        u64 bz = addx2(ldu64(bih + 128 + j0), ldu64(bhh + 128 + j0));
        u64 bi = ldu64(bih + 256 + j0);
        u64 bh = ldu64(bhh + 256 + j0);
#pragma unroll
        for (int p = 0; p < 4; p++) {
            ar[p] = br; az[p] = bz; ain[p] = bi; ahn[p] = bh;
        }
    }
    const float* pa = wf + jp * 4;
    const float* pb = wf + 32768 + jp * 4;
    const float* pc = wf + 65536 + jp * 4;
    ulonglong2 A = *(const ulonglong2*)pa;
    ulonglong2 B = *(const ulonglong2*)pb;
    ulonglong2 C = *(const ulonglong2*)pc;
#pragma unroll 4
    for (int k = 0; k < 128; k++) {
        ulonglong2 Ac = A, Bc = B, Cc = C;
        int kn = (k + 1) & 127;
        A = *(const ulonglong2*)(pa + kn * 256);
        B = *(const ulonglong2*)(pb + kn * 256);
        C = *(const ulonglong2*)(pc + kn * 256);
        const u64* hr = (const u64*)(hsd + k * DUPW + 2 * bB);
        const u64* xr = (const u64*)(xsd + k * DUPW + 2 * bB);
        u64 hd[4] = {hr[0], hr[1], hr[2], hr[3]};
        u64 xd[4] = {xr[0], xr[1], xr[2], xr[3]};
#pragma unroll
        for (int p = 0; p < 4; p++) {
            ffma2(ar[p], hd[p], Ac.x);
            ffma2(az[p], hd[p], Ac.y);
            ffma2(ahn[p], hd[p], Bc.x);
            ffma2(ar[p], xd[p], Bc.y);
            ffma2(az[p], xd[p], Cc.x);
            ffma2(ain[p], xd[p], Cc.y);
        }
    }
    __syncthreads();   // all reads of hsd done before overwrite
    gru_pointwise(ar, az, ain, ahn, hsd, j0, bB);
    __syncthreads();   // hsd ready for next layer
}

// Layer 0 (input dim 4 from duplicated x0s).
__device__ __forceinline__ void gru_layer_0(
    const float* __restrict__ ha, const float* __restrict__ hb,
    const float* __restrict__ xa, const float* __restrict__ xb,
    const float* __restrict__ bih, const float* __restrict__ bhh,
    const float* __restrict__ xsd, float* __restrict__ hsd,
    int jp, int bB)
{
    const int j0 = 2 * jp;
    u64 ar[4], az[4], ain[4], ahn[4];
    {
        u64 br = addx2(ldu64(bih + j0), ldu64(bhh + j0));
        u64 bz = addx2(ldu64(bih + 128 + j0), ldu64(bhh + 128 + j0));
        u64 bi = ldu64(bih + 256 + j0);
        u64 bh = ldu64(bhh + 256 + j0);
#pragma unroll
        for (int p = 0; p < 4; p++) {
            ar[p] = br; az[p] = bz; ain[p] = bi; ahn[p] = bh;
        }
    }
    const float* pa = ha + jp * 4;
    const float* pb = hb + jp * 2;
    ulonglong2 A = *(const ulonglong2*)pa;
    u64 Bv = ldu64(pb);
#pragma unroll 4
    for (int k = 0; k < 128; k++) {
        ulonglong2 Ac = A;
        u64 Bc = Bv;
        int kn = (k + 1) & 127;
        A = *(const ulonglong2*)(pa + kn * 256);
        Bv = ldu64(pb + kn * 128);
        const u64* hr = (const u64*)(hsd + k * DUPW + 2 * bB);
        u64 hd[4] = {hr[0], hr[1], hr[2], hr[3]};
#pragma unroll
        for (int p = 0; p < 4; p++) {
            ffma2(ar[p], hd[p], Ac.x);
            ffma2(az[p], hd[p], Ac.y);
            ffma2(ahn[p], hd[p], Bc);
        }
    }
#pragma unroll
    for (int k = 0; k < 4; k++) {
        ulonglong2 XA = *(const ulonglong2*)(xa + (k * 64 + jp) * 4);
        u64 XB = ldu64(xb + (k * 64 + jp) * 2);
        const u64* xr = (const u64*)(xsd + k * DUPW + 2 * bB);
        u64 xd[4] = {xr[0], xr[1], xr[2], xr[3]};
#pragma unroll
        for (int p = 0; p < 4; p++) {
            ffma2(ar[p], xd[p], XA.x);
            ffma2(az[p], xd[p], XA.y);
            ffma2(ain[p], xd[p], XB);
        }
    }
    __syncthreads();
    gru_pointwise(ar, az, ain, ahn, hsd, j0, bB);
    __syncthreads();
}

__global__ void __launch_bounds__(NTHREADS, 1) gru_main(
    const float* __restrict__ inp, const float* __restrict__ tgt,
    const float* __restrict__ enc_bih, const float* __restrict__ enc_bhh,
    const float* __restrict__ dec_bih, const float* __restrict__ dec_bhh,
    const float* __restrict__ lin1_b, const float* __restrict__ lin2_w,
    const float* __restrict__ lin2_b,
    float* __restrict__ out)
{
    extern __shared__ float sm[];
    float* hsd  = sm;                       // [4][128][DUPW] duplicated
    float* o1s  = sm + 4 * 128 * DUPW;      // [128][34] plain
    float* x0sd = o1s + 128 * 34;           // [4][DUPW] duplicated
    float* red  = x0sd + 4 * DUPW;          // [NTHREADS]

    const int tid  = threadIdx.x;
    const int lane = tid & 31;
    const int w    = tid >> 5;
    const int jp   = ((w & 1) << 5) | lane; // 0..63
    const int j0   = 2 * jp;
    const int bB   = (w >> 1) << 2;         // 4 batch elements per thread
    const int b0   = blockIdx.x * CB;

    for (int u = tid; u < 4 * 128 * DUPW; u += NTHREADS) hsd[u] = 0.0f;
    if (tid < CB * 4) {
        int b = tid >> 2, e = tid & 3;
        out[DEC_OUT_OFF + (size_t)(b0 + b) * 400 + e] =
            inp[(size_t)(b0 + b) * 256 + e];
    }
    __syncthreads();

    // ---------------- encoder: 64 steps ----------------
    for (int t = 0; t < 64; t++) {
        if (tid < CB * 4) {
            int b = tid >> 2, e = tid & 3;
            float xv = inp[(size_t)(b0 + b) * 256 + t * 4 + e];
            x0sd[e * DUPW + 2 * b]     = xv;
            x0sd[e * DUPW + 2 * b + 1] = xv;
        }
        __syncthreads();
        gru_layer_0(g_wt + ENC_L0HA, g_wt + ENC_L0HB,
                    g_wt + ENC_L0XA, g_wt + ENC_L0XB,
                    enc_bih, enc_bhh, x0sd, hsd, jp, bB);
#pragma unroll 1
        for (int l = 1; l < 4; l++) {
            gru_layer_f(g_wt + ENC_F + (l - 1) * 98304,
                        enc_bih + l * 384, enc_bhh + l * 384,
                        hsd + (l - 1) * 128 * DUPW, hsd + l * 128 * DUPW,
                        jp, bB);
        }
        const float* h3 = hsd + 3 * 128 * DUPW;
        for (int u = tid; u < CB * Hh; u += NTHREADS) {
            int b = u >> 7, k = u & 127;
            out[ENC_OUT_OFF + (size_t)(b0 + b) * 8192 + t * 128 + k] =
                h3[k * DUPW + 2 * b];
        }
        // no barrier: next write to hsd[3] / x0sd is many barriers away
    }
    // enc_hidden (L,B,H)
    for (int u = tid; u < 4 * CB * Hh; u += NTHREADS) {
        int l = u >> 12, r = u & 4095, b = r >> 7, k = r & 127;
        out[ENC_HID_OFF + (size_t)l * 524288 + (size_t)(b0 + b) * 128 + k] =
            hsd[l * 128 * DUPW + k * DUPW + 2 * b];
    }

    // ---------------- decoder: 99 steps ----------------
    float lossAcc = 0.0f;
    for (int s = 0; s < 99; s++) {
        if (tid < CB * 4) {
            int b = tid >> 2, e = tid & 3;
            float xv = (s == 0) ? inp[(size_t)(b0 + b) * 256 + e]
                                : tgt[(size_t)(b0 + b) * 400 + s * 4 + e];
            x0sd[e * DUPW + 2 * b]     = xv;
            x0sd[e * DUPW + 2 * b + 1] = xv;
        }
        __syncthreads();
        gru_layer_0(g_wt + DEC_L0HA, g_wt + DEC_L0HB,
                    g_wt + DEC_L0XA, g_wt + DEC_L0XB,
                    dec_bih, dec_bhh, x0sd, hsd, jp, bB);
#pragma unroll 1
        for (int l = 1; l < 4; l++) {
            gru_layer_f(g_wt + DEC_F + (l - 1) * 98304,
                        dec_bih + l * 384, dec_bhh + l * 384,
                        hsd + (l - 1) * 128 * DUPW, hsd + l * 128 * DUPW,
                        jp, bB);
        }
        // lin1 + relu -> o1s (plain layout)
        {
            u64 acc[4];
            u64 bi = ldu64(lin1_b + j0);
#pragma unroll
            for (int p = 0; p < 4; p++) acc[p] = bi;
            const float* top = hsd + 3 * 128 * DUPW;
            const float* pw = g_wt + LIN1P + jp * 2;
            u64 wv = ldu64(pw);
#pragma unroll 4
            for (int k = 0; k < 128; k++) {
                u64 wc = wv;
                int kn = (k + 1) & 127;
                wv = ldu64(pw + kn * 128);
                const u64* tr = (const u64*)(top + k * DUPW + 2 * bB);
                u64 td[4] = {tr[0], tr[1], tr[2], tr[3]};
#pragma unroll
                for (int p = 0; p < 4; p++)
                    ffma2(acc[p], td[p], wc);
            }
#pragma unroll
            for (int p = 0; p < 4; p++) {
                float a0, a1;
                unpack2(acc[p], a0, a1);
                o1s[j0 * 34 + bB + p]       = fmaxf(a0, 0.0f);
                o1s[(j0 + 1) * 34 + bB + p] = fmaxf(a1, 0.0f);
            }
        }
        __syncthreads();
        // lin2 + loss + store
        if (tid < CB * 4) {
            int b = tid >> 2, e = tid & 3;
            float acc = lin2_b[e];
#pragma unroll 4
            for (int i = 0; i < Hh; i++)
                acc = fmaf(o1s[i * 34 + b], lin2_w[e * Hh + i], acc);
            float y = tgt[(size_t)(b0 + b) * 400 + (s + 1) * 4 + e];
            float d = acc - y;
            lossAcc += d * d;
            out[DEC_OUT_OFF + (size_t)(b0 + b) * 400 + (s + 1) * 4 + e] = acc;
        }
        __syncthreads();   // o1s reads done before next step's lin1 writes
    }
    // dec_hidden (L,B,H)
    for (int u = tid; u < 4 * CB * Hh; u += NTHREADS) {
        int l = u >> 12, r = u & 4095, b = r >> 7, k = r & 127;
        out[DEC_HID_OFF + (size_t)l * 524288 + (size_t)(b0 + b) * 128 + k] =
            hsd[l * 128 * DUPW + k * DUPW + 2 * b];
    }

    // loss reduction
    red[tid] = lossAcc;
    __syncthreads();
    for (int s2 = NTHREADS / 2; s2 > 0; s2 >>= 1) {
        if (tid < s2) red[tid] += red[tid + s2];
        __syncthreads();
    }
    if (tid == 0) atomicAdd(out + LOSS_OFF, red[0] * (1.0f / 16384.0f));
}

// ---------------- launch ----------------

extern "C" void kernel_launch(void* const* d_in, const int* in_sizes, int n_in,
                              void* d_out, int out_size)
{
    const float* inp      = (const float*)d_in[0];
    const float* tgt      = (const float*)d_in[1];
    const float* enc_wih0 = (const float*)d_in[2];
    const float* enc_whh0 = (const float*)d_in[3];
    const float* enc_wih  = (const float*)d_in[4];
    const float* enc_whh  = (const float*)d_in[5];
    const float* enc_bih  = (const float*)d_in[6];
    const float* enc_bhh  = (const float*)d_in[7];
    const float* dec_wih0 = (const float*)d_in[8];
    const float* dec_whh0 = (const float*)d_in[9];
    const float* dec_wih  = (const float*)d_in[10];
    const float* dec_whh  = (const float*)d_in[11];
    const float* dec_bih  = (const float*)d_in[12];
    const float* dec_bhh  = (const float*)d_in[13];
    const float* lin1_w   = (const float*)d_in[14];
    const float* lin1_b   = (const float*)d_in[15];
    const float* lin2_w   = (const float*)d_in[16];
    const float* lin2_b   = (const float*)d_in[17];
    float* out = (float*)d_out;

    const int smemBytes =
        (4 * 128 * DUPW + 128 * 34 + 4 * DUPW + NTHREADS) * 4;   // 159808
    cudaFuncSetAttribute(gru_main, cudaFuncAttributeMaxDynamicSharedMemorySize,
                         smemBytes);

    k_zero_loss<<<1, 32>>>(out);

    k_pack_l0<<<16, 512>>>(enc_wih0, enc_whh0,
                           ENC_L0HA, ENC_L0HB, ENC_L0XA, ENC_L0XB);
    k_pack_l0<<<16, 512>>>(dec_wih0, dec_whh0,
                           DEC_L0HA, DEC_L0HB, DEC_L0XA, DEC_L0XB);
    for (int l = 0; l < 3; l++) {
        k_pack_fused<<<16, 512>>>(enc_wih + l * 49152, enc_whh + l * 49152,
                                  ENC_F + l * 98304);
        k_pack_fused<<<16, 512>>>(dec_wih + l * 49152, dec_whh + l * 49152,
                                  DEC_F + l * 98304);
    }
    k_pack_lin1<<<16, 512>>>(lin1_w);

    gru_main<<<NBLOCKS, NTHREADS, smemBytes>>>(
        inp, tgt, enc_bih, enc_bhh, dec_bih, dec_bhh,
        lin1_b, lin2_w, lin2_b, out);
}